// round 8
// baseline (speedup 1.0000x reference)
#include <cuda_runtime.h>
#include <math.h>

// Problem constants (fixed instance)
#define B_   2
#define L_   8192
#define G_   256
#define DG_  8
#define D_   2048          // G_*DG_
#define M_   8192          // complex FFT length (= L)
#define HFS_ 8208          // Hf row stride (>= 8193, 16B-multiple)

// -------- device scratch (static: no runtime allocation allowed) ----------
__device__ __align__(256) float  g_kvt[(size_t)B_ * D_ * L_];  // (B,D,L) kv then y
__device__ __align__(256) float2 g_Hf[(size_t)G_ * HFS_];      // rfft(h_g) bins 0..8192
// spectral constants: g_sp[k] = ( W_k = e^{-i*pi*k/8192} , e^{+i*pi*k/4096} ), k < 4096
__device__ __align__(256) float4 g_sp[4096];
// per-pass twiddle tables: for each (table, p): 4 float4 = {w1,w2},{w3,w4},{w5,w6},{w7,-}
// forward: w_r = e^{-i*pi*r*p*2^(LS+1)/8192}; inverse tables store the conjugate.
#define OF0 0        // fwd LS=0, p<1024
#define OF3 4096     // fwd LS=3, p<128
#define OF6 4608     // fwd LS=6, p<16
#define OF9 4672     // fwd LS=9, p<2
#define OI1 4680     // inv LS=1, p<512
#define OI4 6728     // inv LS=4, p<64
#define OI7 6984     // inv LS=7, p<8
#define TWP_TOTAL 7016
__device__ __align__(256) float4 g_twp4[TWP_TOTAL];

// smem bank swizzle: inject bits 4..7 into the bank field (bits 0..3).
__device__ __forceinline__ int sw(int c){ return c ^ ((c >> 4) & 0xF); }

// -------- complex helpers --------------------------------------------------
__device__ __forceinline__ float2 cadd(float2 a, float2 b){ return make_float2(a.x+b.x, a.y+b.y); }
__device__ __forceinline__ float2 csub(float2 a, float2 b){ return make_float2(a.x-b.x, a.y-b.y); }
__device__ __forceinline__ float2 cmul(float2 a, float2 b){
    return make_float2(a.x*b.x - a.y*b.y, a.x*b.y + a.y*b.x);
}
template<int DIR>
__device__ __forceinline__ float2 jmul(float2 z){
    return (DIR < 0) ? make_float2(z.y, -z.x) : make_float2(-z.y, z.x);
}

// -------- 8-point DFT (kernel e^{DIR*2*pi*i*r*j/8}) ------------------------
template<int DIR>
__device__ __forceinline__ void dft8(const float2 a[8], float2 B[8]){
    const float C = 0.70710678118654752f;
    float2 s0 = cadd(a[0], a[4]), s1 = csub(a[0], a[4]);
    float2 s2 = cadd(a[2], a[6]), s3 = csub(a[2], a[6]);
    float2 e0 = cadd(s0, s2),     e2 = csub(s0, s2);
    float2 js3 = jmul<DIR>(s3);
    float2 e1 = cadd(s1, js3),    e3 = csub(s1, js3);
    float2 u0 = cadd(a[1], a[5]), u1 = csub(a[1], a[5]);
    float2 u2 = cadd(a[3], a[7]), u3 = csub(a[3], a[7]);
    float2 o0 = cadd(u0, u2),     o2 = csub(u0, u2);
    float2 ju3 = jmul<DIR>(u3);
    float2 o1 = cadd(u1, ju3),    o3 = csub(u1, ju3);
    const float2 w1 = make_float2( C, (DIR < 0) ? -C : C);
    const float2 w3 = make_float2(-C, (DIR < 0) ? -C : C);
    float2 t1 = cmul(w1, o1);
    float2 t2 = jmul<DIR>(o2);
    float2 t3 = cmul(w3, o3);
    B[0] = cadd(e0, o0); B[4] = csub(e0, o0);
    B[1] = cadd(e1, t1); B[5] = csub(e1, t1);
    B[2] = cadd(e2, t2); B[6] = csub(e2, t2);
    B[3] = cadd(e3, t3); B[7] = csub(e3, t3);
}

// load 7 twiddles (w[1..7]) for butterfly index p from a packed table
__device__ __forceinline__ void load_tw(const float4* __restrict__ tb, int p, float2 w[8]){
    const float4* tp = tb + 4 * p;
    float4 q0 = __ldg(tp + 0), q1 = __ldg(tp + 1), q2 = __ldg(tp + 2), q3 = __ldg(tp + 3);
    w[1] = make_float2(q0.x, q0.y); w[2] = make_float2(q0.z, q0.w);
    w[3] = make_float2(q1.x, q1.y); w[4] = make_float2(q1.z, q1.w);
    w[5] = make_float2(q2.x, q2.y); w[6] = make_float2(q2.z, q2.w);
    w[7] = make_float2(q3.x, q3.y);
}

// -------- mid radix-8 Stockham pass (smem -> smem), s = 1<<LS --------------
// requires blockDim.x == 1024 ; twiddles (incl. inverse conj) come from table
template<int DIR, int LS>
__device__ __forceinline__ void pass_smem(const float2* __restrict__ x,
                                          float2* __restrict__ y,
                                          const float4* __restrict__ tb){
    const int t  = threadIdx.x;
    const int q  = t & ((1 << LS) - 1);
    const int p  = t >> LS;
    float2 w[8];
    load_tw(tb, p, w);                         // LDG issues first, overlaps LDS+dft8
    const int xs = sw(t);                      // sw(t+1024j) = sw(t)+1024j
    float2 a[8];
    #pragma unroll
    for (int j = 0; j < 8; j++) a[j] = x[xs + 1024 * j];
    float2 Bv[8];
    dft8<DIR>(a, Bv);
    const int base = q + (p << (LS + 3));
    if constexpr (LS >= 8){
        const int sb = sw(base);               // r<<LS disjoint from swizzle bits
        y[sb] = Bv[0];
        #pragma unroll
        for (int r = 1; r < 8; r++) y[sb + (r << LS)] = cmul(w[r], Bv[r]);
    } else {
        y[sw(base)] = Bv[0];
        #pragma unroll
        for (int r = 1; r < 8; r++) y[sw(base + (r << LS))] = cmul(w[r], Bv[r]);
    }
}

// -------- first forward pass: gmem -> smem, LS=0, upper half zero ----------
__device__ __forceinline__ void pass_first_gmem(const float2* __restrict__ g,
                                                float2* __restrict__ y){
    const int t = threadIdx.x;
    float2 w[8];
    load_tw(g_twp4 + OF0, t, w);
    float2 a[8];
    #pragma unroll
    for (int j = 0; j < 4; j++) a[j] = __ldg(g + t + 1024 * j);
    #pragma unroll
    for (int j = 4; j < 8; j++) a[j] = make_float2(0.f, 0.f);
    float2 Bv[8];
    dft8<-1>(a, Bv);
    const int base = t << 3;
    const int m = (base >> 4) & 0xF;           // constant across r<8; XOR per index
    y[base ^ m] = Bv[0];
    #pragma unroll
    for (int r = 1; r < 8; r++) y[(base + r) ^ m] = cmul(w[r], Bv[r]);
}

// -------- last inverse pass: smem -> gmem, s=1024 => p=0 => unit twiddles --
// only n = t + 1024r < 4096 (r<4) needed (packed-real output); 1/8192 folded
__device__ __forceinline__ void pass_last_inv_gmem(const float2* __restrict__ x,
                                                   float2* __restrict__ g){
    const int t  = threadIdx.x;
    const int xs = sw(t);
    float2 a[8];
    #pragma unroll
    for (int j = 0; j < 8; j++) a[j] = x[xs + 1024 * j];
    float2 Bv[8];
    dft8<+1>(a, Bv);
    const float sc = 1.0f / 8192.0f;
    #pragma unroll
    for (int r = 0; r < 4; r++)
        g[t + 1024 * r] = make_float2(Bv[r].x * sc, Bv[r].y * sc);
}

// -------- Hermitian unpack/repack helpers (packed-real trick) ---------------
__device__ __forceinline__ void herm_unpack(float2 Zk, float2 Zm, float2 Wk,
                                            float2& Xk, float2& Xm){
    float2 Ze = make_float2(0.5f*(Zk.x + Zm.x), 0.5f*(Zk.y - Zm.y));
    float2 Zo = make_float2(0.5f*(Zk.y + Zm.y), -0.5f*(Zk.x - Zm.x));
    float2 WZo = cmul(Wk, Zo);
    Xk = cadd(Ze, WZo);
    Xm = csub(Ze, WZo); Xm.y = -Xm.y;          // conj
}
__device__ __forceinline__ void herm_repack(float2 Yk, float2 Ym, float2 Wk,
                                            float2& Ck, float2& Cm){
    float2 Ze2 = make_float2(0.5f*(Yk.x + Ym.x), 0.5f*(Yk.y - Ym.y));
    float2 T   = make_float2(0.5f*(Yk.x - Ym.x), 0.5f*(Yk.y + Ym.y));
    float2 Wc  = make_float2(Wk.x, -Wk.y);
    float2 Zo2 = cmul(Wc, T);
    Ck = make_float2(Ze2.x - Zo2.y,  Ze2.y + Zo2.x);
    Cm = make_float2(Ze2.x + Zo2.y, -Ze2.y + Zo2.x);
}

// -------- setup: spectral constants ----------------------------------------
__global__ void sp_kernel(){
    int k = blockIdx.x * 256 + threadIdx.x;
    if (k < 4096){
        double s1, c1, s2, c2;
        sincospi(-(double)k / 8192.0, &s1, &c1);   // W_k
        sincospi( (double)k / 4096.0, &s2, &c2);   // e^{+i*pi*k/4096} = conj(tw[2k])
        g_sp[k] = make_float4((float)c1, (float)s1, (float)c2, (float)s2);
    }
}

// -------- setup: per-pass twiddle tables ------------------------------------
__global__ void twp_kernel(){
    int i = blockIdx.x * 256 + threadIdx.x;
    if (i >= 1754) return;
    int off, LS, p; double sgn;
    if      (i < 1024){ off = OF0; LS = 0; sgn = -1.0; p = i; }
    else if (i < 1152){ off = OF3; LS = 3; sgn = -1.0; p = i - 1024; }
    else if (i < 1168){ off = OF6; LS = 6; sgn = -1.0; p = i - 1152; }
    else if (i < 1170){ off = OF9; LS = 9; sgn = -1.0; p = i - 1168; }
    else if (i < 1682){ off = OI1; LS = 1; sgn =  1.0; p = i - 1170; }
    else if (i < 1746){ off = OI4; LS = 4; sgn =  1.0; p = i - 1682; }
    else              { off = OI7; LS = 7; sgn =  1.0; p = i - 1746; }
    float2 w[8];
    double step = (double)((long long)p << (LS + 1)) / 8192.0;
    #pragma unroll
    for (int r = 1; r < 8; r++){
        double s, c;
        sincospi(sgn * r * step, &s, &c);
        w[r] = make_float2((float)c, (float)s);
    }
    float4* dst = g_twp4 + off + 4 * p;
    dst[0] = make_float4(w[1].x, w[1].y, w[2].x, w[2].y);
    dst[1] = make_float4(w[3].x, w[3].y, w[4].x, w[4].y);
    dst[2] = make_float4(w[5].x, w[5].y, w[6].x, w[6].y);
    dst[3] = make_float4(w[7].x, w[7].y, 0.f, 0.f);
}

// -------- Hf = rfft(h_g, 16384), bins 0..8192 ------------------------------
__global__ void __launch_bounds__(1024) hf_kernel(const float* __restrict__ h){
    extern __shared__ float2 sm[];
    float2* a = sm;
    float2* b = sm + M_;
    const int g = blockIdx.x;
    const float2* h2 = reinterpret_cast<const float2*>(h + (size_t)g * L_);

    pass_first_gmem(h2, a);                 __syncthreads();
    pass_smem<-1, 3>(a, b, g_twp4 + OF3);   __syncthreads();
    pass_smem<-1, 6>(b, a, g_twp4 + OF6);   __syncthreads();
    pass_smem<-1, 9>(a, b, g_twp4 + OF9);   __syncthreads();
    // b holds A ; Z[t] = A[t] + A[t+4096], Z[t+4096] = A[t] - A[t+4096]
    float2* Hf = g_Hf + (size_t)g * HFS_;
    for (int k = threadIdx.x; k < 2048; k += 1024){
        if (k == 0){
            float2 A0 = b[0],    A1 = b[4096];
            float2 A2 = b[2048], A3 = b[6144];   // sw() identity here
            float2 Z0 = cadd(A0, A1), Z4 = csub(A0, A1);
            float2 Z2 = cadd(A2, A3), Z6 = csub(A2, A3);
            Hf[0]    = make_float2(Z0.x + Z0.y, 0.f);
            Hf[8192] = make_float2(Z0.x - Z0.y, 0.f);
            Hf[4096] = make_float2(Z4.x, -Z4.y);
            float4 sc2 = __ldg(g_sp + 2048);
            float2 Xk, Xm;
            herm_unpack(Z2, Z6, make_float2(sc2.x, sc2.y), Xk, Xm);
            Hf[2048] = Xk; Hf[6144] = Xm;
        } else {
            const int k2 = 4096 - k;
            const int s1 = sw(k), s2 = sw(k2);
            float4 spk  = __ldg(g_sp + k);
            float4 spk2 = __ldg(g_sp + k2);
            float2 A0 = b[s1], A1 = b[s1 + 4096];
            float2 A2 = b[s2], A3 = b[s2 + 4096];
            float2 Zk  = cadd(A0, A1);
            float2 Zk4 = csub(A0, A1);
            float2 Zk2 = cadd(A2, A3);
            float2 Zm  = csub(A2, A3);
            float2 Xk, Xm, Xk2, Xk4;
            herm_unpack(Zk,  Zm,  make_float2(spk.x,  spk.y),  Xk,  Xm);
            herm_unpack(Zk2, Zk4, make_float2(spk2.x, spk2.y), Xk2, Xk4);
            Hf[k] = Xk;   Hf[8192 - k] = Xm;
            Hf[k2] = Xk2; Hf[4096 + k] = Xk4;
        }
    }
}

// -------- pregate + transpose: kv_t(b,d,l) = x2(b,l,d)*v(b,l,d) ------------
// 64x64 tiles, block (16,16): 4 float4 in flight per thread per phase
__global__ void pregate_transpose(const float* __restrict__ x2,
                                  const float* __restrict__ v){
    __shared__ float tile[64][65];               // [l-local][d-local]
    const int b  = blockIdx.z;
    const int l0 = blockIdx.x * 64;
    const int d0 = blockIdx.y * 64;
    const int tx = threadIdx.x;                  // 0..15
    const int ty = threadIdx.y;                  // 0..15
    #pragma unroll
    for (int i = 0; i < 4; i++){
        int lr = ty + 16 * i;
        size_t idx = ((size_t)b * L_ + (l0 + lr)) * D_ + d0 + 4 * tx;
        float4 xa = *reinterpret_cast<const float4*>(x2 + idx);
        float4 va = *reinterpret_cast<const float4*>(v  + idx);
        tile[lr][4*tx + 0] = xa.x * va.x;
        tile[lr][4*tx + 1] = xa.y * va.y;
        tile[lr][4*tx + 2] = xa.z * va.z;
        tile[lr][4*tx + 3] = xa.w * va.w;
    }
    __syncthreads();
    #pragma unroll
    for (int i = 0; i < 4; i++){
        int dr = ty + 16 * i;
        float4 o;
        o.x = tile[4*tx + 0][dr];
        o.y = tile[4*tx + 1][dr];
        o.z = tile[4*tx + 2][dr];
        o.w = tile[4*tx + 3][dr];
        *reinterpret_cast<float4*>(g_kvt + ((size_t)b * D_ + d0 + dr) * L_ + l0 + 4 * tx) = o;
    }
}

// -------- per-channel FFT convolution --------------------------------------
__global__ void __launch_bounds__(1024) conv_kernel(const float* __restrict__ bias){
    extern __shared__ float2 sm[];
    float2* a = sm;
    float2* b = sm + M_;
    const int c = blockIdx.x;                 // c = bidx*D + d
    const int d = c & (D_ - 1);
    const int g = d >> 3;                     // DG_ = 8
    const float bs = __ldg(bias + d);
    const float2* kv2 = reinterpret_cast<const float2*>(g_kvt + (size_t)c * L_);

    // forward: gmem-fused first pass + 3 smem passes (r2 folded into spectral)
    pass_first_gmem(kv2, a);                __syncthreads();
    pass_smem<-1, 3>(a, b, g_twp4 + OF3);   __syncthreads();
    pass_smem<-1, 6>(b, a, g_twp4 + OF6);   __syncthreads();
    pass_smem<-1, 9>(a, b, g_twp4 + OF9);   __syncthreads();

    // spectral: fwd r2 fold + Hermitian * (H+bias) + repack + inv r2 fold
    const float2* Hf = g_Hf + (size_t)g * HFS_;
    for (int k = threadIdx.x; k < 2048; k += 1024){
        if (k == 0){
            float2 A0 = b[0],    A1 = b[4096];
            float2 A2 = b[2048], A3 = b[6144];
            float2 Z0 = cadd(A0, A1), Z4 = csub(A0, A1);
            float2 Z2 = cadd(A2, A3), Z6 = csub(A2, A3);
            float X0 = Z0.x + Z0.y, X8 = Z0.x - Z0.y;
            float Y0 = X0 * (__ldg(&Hf[0].x)    + bs);
            float Y8 = X8 * (__ldg(&Hf[8192].x) + bs);
            float2 C0 = make_float2(0.5f*(Y0 + Y8), 0.5f*(Y0 - Y8));
            float2 X4 = make_float2(Z4.x, -Z4.y);
            float2 G4 = __ldg(&Hf[4096]); G4.x += bs;
            float2 Y4 = cmul(X4, G4);
            float2 C4 = make_float2(Y4.x, -Y4.y);
            float4 sc2 = __ldg(g_sp + 2048);     // (W2048, e^{+i*pi/2})
            float2 W2 = make_float2(sc2.x, sc2.y);
            float2 Xk, Xm;
            herm_unpack(Z2, Z6, W2, Xk, Xm);
            float2 Gk = __ldg(&Hf[2048]); Gk.x += bs;
            float2 Gm = __ldg(&Hf[6144]); Gm.x += bs;
            float2 C2, C6;
            herm_repack(cmul(Xk, Gk), cmul(Xm, Gm), W2, C2, C6);
            a[0] = cadd(C0, C4);
            a[1] = csub(C0, C4);
            float2 w = make_float2(sc2.z, sc2.w);
            a[4096] = cadd(C2, C6);
            a[4097] = cmul(w, csub(C2, C6));
        } else {
            const int k2 = 4096 - k;
            const int s1 = sw(k), s2 = sw(k2);
            float4 spk  = __ldg(g_sp + k);       // (Wk, wA)
            float4 spk2 = __ldg(g_sp + k2);      // (Wk2, wB)
            float2 Gk  = __ldg(&Hf[k]);        Gk.x  += bs;
            float2 Gm  = __ldg(&Hf[8192 - k]); Gm.x  += bs;
            float2 Gk2 = __ldg(&Hf[k2]);       Gk2.x += bs;
            float2 Gk4 = __ldg(&Hf[4096 + k]); Gk4.x += bs;
            float2 A0 = b[s1], A1 = b[s1 + 4096];
            float2 A2 = b[s2], A3 = b[s2 + 4096];
            float2 Zk  = cadd(A0, A1);
            float2 Zk4 = csub(A0, A1);
            float2 Zk2 = cadd(A2, A3);
            float2 Zm  = csub(A2, A3);
            float2 Wk  = make_float2(spk.x,  spk.y);
            float2 Wk2 = make_float2(spk2.x, spk2.y);
            float2 Xk, Xm, Xk2, Xk4;
            herm_unpack(Zk,  Zm,  Wk,  Xk,  Xm);
            herm_unpack(Zk2, Zk4, Wk2, Xk2, Xk4);
            float2 Ck, Cm, Ck2, Ck4;
            herm_repack(cmul(Xk,  Gk),  cmul(Xm,  Gm),  Wk,  Ck,  Cm);
            herm_repack(cmul(Xk2, Gk2), cmul(Xk4, Gk4), Wk2, Ck2, Ck4);
            // inverse radix-2 fold (s=1): p=k -> 2k,2k+1 ; p=k2 -> 2k2,2k2+1
            int o1 = sw(2 * k);
            float2 wA = make_float2(spk.z, spk.w);
            a[o1]     = cadd(Ck, Ck4);
            a[o1 ^ 1] = cmul(wA, csub(Ck, Ck4));
            int o2 = sw(2 * k2);
            float2 wB = make_float2(spk2.z, spk2.w);
            a[o2]     = cadd(Ck2, Cm);
            a[o2 ^ 1] = cmul(wB, csub(Ck2, Cm));
        }
    }
    __syncthreads();

    // inverse: 3 smem passes + final pass fused with gmem store (r<4 only)
    pass_smem<+1, 1>(a, b, g_twp4 + OI1);   __syncthreads();
    pass_smem<+1, 4>(b, a, g_twp4 + OI4);   __syncthreads();
    pass_smem<+1, 7>(a, b, g_twp4 + OI7);   __syncthreads();
    float2* out2 = reinterpret_cast<float2*>(g_kvt + (size_t)c * L_);
    pass_last_inv_gmem(b, out2);
}

// -------- gate + transpose back: out(b,l,d) = x1(b,l,d) * y_t(b,d,l) -------
__global__ void gate_transpose(const float* __restrict__ x1,
                               float* __restrict__ out){
    __shared__ float tile[64][65];               // [l-local][d-local]
    const int b  = blockIdx.z;
    const int l0 = blockIdx.x * 64;
    const int d0 = blockIdx.y * 64;
    const int tx = threadIdx.x;                  // 0..15
    const int ty = threadIdx.y;                  // 0..15
    #pragma unroll
    for (int i = 0; i < 4; i++){
        int dr = ty + 16 * i;
        float4 ya = *reinterpret_cast<const float4*>(
            g_kvt + ((size_t)b * D_ + d0 + dr) * L_ + l0 + 4 * tx);
        tile[4*tx + 0][dr] = ya.x;
        tile[4*tx + 1][dr] = ya.y;
        tile[4*tx + 2][dr] = ya.z;
        tile[4*tx + 3][dr] = ya.w;
    }
    __syncthreads();
    #pragma unroll
    for (int i = 0; i < 4; i++){
        int lr = ty + 16 * i;
        size_t idx = ((size_t)b * L_ + (l0 + lr)) * D_ + d0 + 4 * tx;
        float4 xa = *reinterpret_cast<const float4*>(x1 + idx);
        float4 o;
        o.x = xa.x * tile[lr][4*tx + 0];
        o.y = xa.y * tile[lr][4*tx + 1];
        o.z = xa.z * tile[lr][4*tx + 2];
        o.w = xa.w * tile[lr][4*tx + 3];
        *reinterpret_cast<float4*>(out + idx) = o;
    }
}

// ---------------------------------------------------------------------------
extern "C" void kernel_launch(void* const* d_in, const int* in_sizes, int n_in,
                              void* d_out, int out_size){
    const float* x1   = (const float*)d_in[0];
    const float* x2   = (const float*)d_in[1];
    const float* v    = (const float*)d_in[2];
    const float* h    = (const float*)d_in[3];
    const float* bias = (const float*)d_in[4];
    float* out = (float*)d_out;

    const int SMEM = 2 * M_ * (int)sizeof(float2);   // 131072 B
    cudaFuncSetAttribute(hf_kernel,   cudaFuncAttributeMaxDynamicSharedMemorySize, SMEM);
    cudaFuncSetAttribute(conv_kernel, cudaFuncAttributeMaxDynamicSharedMemorySize, SMEM);

    sp_kernel<<<16, 256>>>();
    twp_kernel<<<7, 256>>>();
    hf_kernel<<<G_, 1024, SMEM>>>(h);

    dim3 tgrid(L_ / 64, D_ / 64, B_);
    dim3 tblk(16, 16);
    pregate_transpose<<<tgrid, tblk>>>(x2, v);

    conv_kernel<<<B_ * D_, 1024, SMEM>>>(bias);

    gate_transpose<<<tgrid, tblk>>>(x1, out);
}

// round 10
// speedup vs baseline: 1.0722x; 1.0722x over previous
#include <cuda_runtime.h>
#include <math.h>

// Problem constants (fixed instance)
#define B_   2
#define L_   8192
#define G_   256
#define DG_  8
#define D_   2048          // G_*DG_
#define M_   8192          // complex FFT length (= L)
#define HFS_ 8208          // Hf row stride (>= 8193, 16B-multiple)

// -------- device scratch (static: no runtime allocation allowed) ----------
__device__ __align__(256) float  g_kvt[(size_t)B_ * D_ * L_];  // (B,D,L) kv then y
__device__ __align__(256) float2 g_Hf[(size_t)G_ * HFS_];      // rfft(h_g) bins 0..8192
__device__ __align__(256) float2 g_tw[M_];                     // e^{-2*pi*i*k/16384}
// spectral constants: g_sp[k] = ( W_k = e^{-i*pi*k/8192} , e^{+i*pi*k/4096} ), k < 4096
__device__ __align__(256) float4 g_sp[4096];
// broadcast twiddle tables (per p: 4 float4 = w1..w7), only for LS>=3 passes
#define OF3 0        // fwd LS=3, p<128
#define OF6 512      // fwd LS=6, p<16
#define OF9 576      // fwd LS=9, p<2
#define OI4 584      // inv LS=4, p<64
#define OI7 840      // inv LS=7, p<8
#define TWP_TOTAL 872
__device__ __align__(256) float4 g_twp4[TWP_TOTAL];

// smem bank swizzle: inject bits 4..7 into the bank field (bits 0..3).
__device__ __forceinline__ int sw(int c){ return c ^ ((c >> 4) & 0xF); }

// -------- complex helpers --------------------------------------------------
__device__ __forceinline__ float2 cadd(float2 a, float2 b){ return make_float2(a.x+b.x, a.y+b.y); }
__device__ __forceinline__ float2 csub(float2 a, float2 b){ return make_float2(a.x-b.x, a.y-b.y); }
__device__ __forceinline__ float2 cmul(float2 a, float2 b){
    return make_float2(a.x*b.x - a.y*b.y, a.x*b.y + a.y*b.x);
}
template<int DIR>
__device__ __forceinline__ float2 jmul(float2 z){
    return (DIR < 0) ? make_float2(z.y, -z.x) : make_float2(-z.y, z.x);
}

// -------- 8-point DFT (kernel e^{DIR*2*pi*i*r*j/8}) ------------------------
template<int DIR>
__device__ __forceinline__ void dft8(const float2 a[8], float2 B[8]){
    const float C = 0.70710678118654752f;
    float2 s0 = cadd(a[0], a[4]), s1 = csub(a[0], a[4]);
    float2 s2 = cadd(a[2], a[6]), s3 = csub(a[2], a[6]);
    float2 e0 = cadd(s0, s2),     e2 = csub(s0, s2);
    float2 js3 = jmul<DIR>(s3);
    float2 e1 = cadd(s1, js3),    e3 = csub(s1, js3);
    float2 u0 = cadd(a[1], a[5]), u1 = csub(a[1], a[5]);
    float2 u2 = cadd(a[3], a[7]), u3 = csub(a[3], a[7]);
    float2 o0 = cadd(u0, u2),     o2 = csub(u0, u2);
    float2 ju3 = jmul<DIR>(u3);
    float2 o1 = cadd(u1, ju3),    o3 = csub(u1, ju3);
    const float2 w1 = make_float2( C, (DIR < 0) ? -C : C);
    const float2 w3 = make_float2(-C, (DIR < 0) ? -C : C);
    float2 t1 = cmul(w1, o1);
    float2 t2 = jmul<DIR>(o2);
    float2 t3 = cmul(w3, o3);
    B[0] = cadd(e0, o0); B[4] = csub(e0, o0);
    B[1] = cadd(e1, t1); B[5] = csub(e1, t1);
    B[2] = cadd(e2, t2); B[6] = csub(e2, t2);
    B[3] = cadd(e3, t3); B[7] = csub(e3, t3);
}

// log-depth twiddle powers: w[r] = w1^r
__device__ __forceinline__ void twpowers(float2 w1, float2 w[8]){
    w[1] = w1;
    w[2] = cmul(w1, w1);
    w[3] = cmul(w1, w[2]);
    w[4] = cmul(w[2], w[2]);
    w[5] = cmul(w[2], w[3]);
    w[6] = cmul(w[3], w[3]);
    w[7] = cmul(w[3], w[4]);
}

// load 7 twiddles from a broadcast table (one 64B row per p; p shared by >=8 lanes)
__device__ __forceinline__ void load_tw(const float4* __restrict__ tb, int p, float2 w[8]){
    const float4* tp = tb + 4 * p;
    float4 q0 = __ldg(tp + 0), q1 = __ldg(tp + 1), q2 = __ldg(tp + 2), q3 = __ldg(tp + 3);
    w[1] = make_float2(q0.x, q0.y); w[2] = make_float2(q0.z, q0.w);
    w[3] = make_float2(q1.x, q1.y); w[4] = make_float2(q1.z, q1.w);
    w[5] = make_float2(q2.x, q2.y); w[6] = make_float2(q2.z, q2.w);
    w[7] = make_float2(q3.x, q3.y);
}

// -------- mid radix-8 Stockham pass (smem -> smem), s = 1<<LS --------------
// requires blockDim.x == 1024. TB: broadcast table (LS>=3) or nullptr => compute
template<int DIR, int LS, bool USE_TABLE>
__device__ __forceinline__ void pass_smem(const float2* __restrict__ x,
                                          float2* __restrict__ y,
                                          const float4* __restrict__ tb){
    const int t  = threadIdx.x;
    const int q  = t & ((1 << LS) - 1);
    const int p  = t >> LS;
    float2 w[8];
    if constexpr (USE_TABLE){
        load_tw(tb, p, w);                     // issues early, overlaps LDS+dft8
    }
    const int xs = sw(t);                      // sw(t+1024j) = sw(t)+1024j
    float2 a[8];
    #pragma unroll
    for (int j = 0; j < 8; j++) a[j] = x[xs + 1024 * j];
    if constexpr (!USE_TABLE){
        float2 w1 = g_tw[p << (LS + 1)];
        if (DIR > 0) w1.y = -w1.y;
        twpowers(w1, w);
    }
    float2 Bv[8];
    dft8<DIR>(a, Bv);
    const int base = q + (p << (LS + 3));
    if constexpr (LS >= 8){
        const int sb = sw(base);               // r<<LS disjoint from swizzle bits
        y[sb] = Bv[0];
        #pragma unroll
        for (int r = 1; r < 8; r++) y[sb + (r << LS)] = cmul(w[r], Bv[r]);
    } else {
        y[sw(base)] = Bv[0];
        #pragma unroll
        for (int r = 1; r < 8; r++) y[sw(base + (r << LS))] = cmul(w[r], Bv[r]);
    }
}

// -------- first forward pass: gmem -> smem, LS=0, upper half zero ----------
// distinct p per thread -> computed twiddles (table would be latency-bound)
__device__ __forceinline__ void pass_first_gmem(const float2* __restrict__ g,
                                                float2* __restrict__ y){
    const int t = threadIdx.x;
    float2 a[8];
    #pragma unroll
    for (int j = 0; j < 4; j++) a[j] = __ldg(g + t + 1024 * j);
    #pragma unroll
    for (int j = 4; j < 8; j++) a[j] = make_float2(0.f, 0.f);
    float2 Bv[8];
    dft8<-1>(a, Bv);
    float2 w[8];
    twpowers(g_tw[t << 1], w);
    const int base = t << 3;
    const int m = (base >> 4) & 0xF;           // constant across r<8; XOR per index
    y[base ^ m] = Bv[0];
    #pragma unroll
    for (int r = 1; r < 8; r++) y[(base + r) ^ m] = cmul(w[r], Bv[r]);
}

// -------- last inverse pass: smem -> gmem, s=1024 => p=0 => unit twiddles --
// only n = t + 1024r < 4096 (r<4) needed (packed-real output); 1/8192 folded
__device__ __forceinline__ void pass_last_inv_gmem(const float2* __restrict__ x,
                                                   float2* __restrict__ g){
    const int t  = threadIdx.x;
    const int xs = sw(t);
    float2 a[8];
    #pragma unroll
    for (int j = 0; j < 8; j++) a[j] = x[xs + 1024 * j];
    float2 Bv[8];
    dft8<+1>(a, Bv);
    const float sc = 1.0f / 8192.0f;
    #pragma unroll
    for (int r = 0; r < 4; r++)
        g[t + 1024 * r] = make_float2(Bv[r].x * sc, Bv[r].y * sc);
}

// -------- Hermitian unpack/repack helpers (packed-real trick) ---------------
__device__ __forceinline__ void herm_unpack(float2 Zk, float2 Zm, float2 Wk,
                                            float2& Xk, float2& Xm){
    float2 Ze = make_float2(0.5f*(Zk.x + Zm.x), 0.5f*(Zk.y - Zm.y));
    float2 Zo = make_float2(0.5f*(Zk.y + Zm.y), -0.5f*(Zk.x - Zm.x));
    float2 WZo = cmul(Wk, Zo);
    Xk = cadd(Ze, WZo);
    Xm = csub(Ze, WZo); Xm.y = -Xm.y;          // conj
}
__device__ __forceinline__ void herm_repack(float2 Yk, float2 Ym, float2 Wk,
                                            float2& Ck, float2& Cm){
    float2 Ze2 = make_float2(0.5f*(Yk.x + Ym.x), 0.5f*(Yk.y - Ym.y));
    float2 T   = make_float2(0.5f*(Yk.x - Ym.x), 0.5f*(Yk.y + Ym.y));
    float2 Wc  = make_float2(Wk.x, -Wk.y);
    float2 Zo2 = cmul(Wc, T);
    Ck = make_float2(Ze2.x - Zo2.y,  Ze2.y + Zo2.x);
    Cm = make_float2(Ze2.x + Zo2.y, -Ze2.y + Zo2.x);
}

// -------- setup kernels -----------------------------------------------------
__global__ void tw_kernel(){
    int k = blockIdx.x * 256 + threadIdx.x;
    if (k < M_){
        double s, c;
        sincospi(-(double)k / 8192.0, &s, &c);   // -2*pi*k/16384
        g_tw[k] = make_float2((float)c, (float)s);
    }
}
__global__ void sp_kernel(){
    int k = blockIdx.x * 256 + threadIdx.x;
    if (k < 4096){
        double s1, c1, s2, c2;
        sincospi(-(double)k / 8192.0, &s1, &c1);   // W_k
        sincospi( (double)k / 4096.0, &s2, &c2);   // e^{+i*pi*k/4096}
        g_sp[k] = make_float4((float)c1, (float)s1, (float)c2, (float)s2);
    }
}
__global__ void twp_kernel(){
    int i = blockIdx.x * 256 + threadIdx.x;
    if (i >= 218) return;
    int off, LS, p; double sgn;
    if      (i < 128){ off = OF3; LS = 3; sgn = -1.0; p = i; }
    else if (i < 144){ off = OF6; LS = 6; sgn = -1.0; p = i - 128; }
    else if (i < 146){ off = OF9; LS = 9; sgn = -1.0; p = i - 144; }
    else if (i < 210){ off = OI4; LS = 4; sgn =  1.0; p = i - 146; }
    else              { off = OI7; LS = 7; sgn =  1.0; p = i - 210; }
    float2 w[8];
    double step = (double)((long long)p << (LS + 1)) / 8192.0;
    #pragma unroll
    for (int r = 1; r < 8; r++){
        double s, c;
        sincospi(sgn * r * step, &s, &c);
        w[r] = make_float2((float)c, (float)s);
    }
    float4* dst = g_twp4 + off + 4 * p;
    dst[0] = make_float4(w[1].x, w[1].y, w[2].x, w[2].y);
    dst[1] = make_float4(w[3].x, w[3].y, w[4].x, w[4].y);
    dst[2] = make_float4(w[5].x, w[5].y, w[6].x, w[6].y);
    dst[3] = make_float4(w[7].x, w[7].y, 0.f, 0.f);
}

// -------- Hf = rfft(h_g, 16384), bins 0..8192 ------------------------------
__global__ void __launch_bounds__(1024) hf_kernel(const float* __restrict__ h){
    extern __shared__ float2 sm[];
    float2* a = sm;
    float2* b = sm + M_;
    const int g = blockIdx.x;
    const float2* h2 = reinterpret_cast<const float2*>(h + (size_t)g * L_);

    pass_first_gmem(h2, a);                       __syncthreads();
    pass_smem<-1, 3, true>(a, b, g_twp4 + OF3);   __syncthreads();
    pass_smem<-1, 6, true>(b, a, g_twp4 + OF6);   __syncthreads();
    pass_smem<-1, 9, true>(a, b, g_twp4 + OF9);   __syncthreads();
    // b holds A ; Z[t] = A[t] + A[t+4096], Z[t+4096] = A[t] - A[t+4096]
    float2* Hf = g_Hf + (size_t)g * HFS_;
    for (int k = threadIdx.x; k < 2048; k += 1024){
        if (k == 0){
            float2 A0 = b[0],    A1 = b[4096];
            float2 A2 = b[2048], A3 = b[6144];   // sw() identity here
            float2 Z0 = cadd(A0, A1), Z4 = csub(A0, A1);
            float2 Z2 = cadd(A2, A3), Z6 = csub(A2, A3);
            Hf[0]    = make_float2(Z0.x + Z0.y, 0.f);
            Hf[8192] = make_float2(Z0.x - Z0.y, 0.f);
            Hf[4096] = make_float2(Z4.x, -Z4.y);
            float4 sc2 = __ldg(g_sp + 2048);
            float2 Xk, Xm;
            herm_unpack(Z2, Z6, make_float2(sc2.x, sc2.y), Xk, Xm);
            Hf[2048] = Xk; Hf[6144] = Xm;
        } else {
            const int k2 = 4096 - k;
            const int s1 = sw(k), s2 = sw(k2);
            float4 spk  = __ldg(g_sp + k);
            float4 spk2 = __ldg(g_sp + k2);
            float2 A0 = b[s1], A1 = b[s1 + 4096];
            float2 A2 = b[s2], A3 = b[s2 + 4096];
            float2 Zk  = cadd(A0, A1);
            float2 Zk4 = csub(A0, A1);
            float2 Zk2 = cadd(A2, A3);
            float2 Zm  = csub(A2, A3);
            float2 Xk, Xm, Xk2, Xk4;
            herm_unpack(Zk,  Zm,  make_float2(spk.x,  spk.y),  Xk,  Xm);
            herm_unpack(Zk2, Zk4, make_float2(spk2.x, spk2.y), Xk2, Xk4);
            Hf[k] = Xk;   Hf[8192 - k] = Xm;
            Hf[k2] = Xk2; Hf[4096 + k] = Xk4;
        }
    }
}

// -------- pregate + transpose: kv_t(b,d,l) = x2(b,l,d)*v(b,l,d) ------------
// 64x64 tiles, block (16,16): 4 float4 in flight per thread per phase
__global__ void pregate_transpose(const float* __restrict__ x2,
                                  const float* __restrict__ v){
    __shared__ float tile[64][65];               // [l-local][d-local]
    const int b  = blockIdx.z;
    const int l0 = blockIdx.x * 64;
    const int d0 = blockIdx.y * 64;
    const int tx = threadIdx.x;                  // 0..15
    const int ty = threadIdx.y;                  // 0..15
    #pragma unroll
    for (int i = 0; i < 4; i++){
        int lr = ty + 16 * i;
        size_t idx = ((size_t)b * L_ + (l0 + lr)) * D_ + d0 + 4 * tx;
        float4 xa = *reinterpret_cast<const float4*>(x2 + idx);
        float4 va = *reinterpret_cast<const float4*>(v  + idx);
        tile[lr][4*tx + 0] = xa.x * va.x;
        tile[lr][4*tx + 1] = xa.y * va.y;
        tile[lr][4*tx + 2] = xa.z * va.z;
        tile[lr][4*tx + 3] = xa.w * va.w;
    }
    __syncthreads();
    #pragma unroll
    for (int i = 0; i < 4; i++){
        int dr = ty + 16 * i;
        float4 o;
        o.x = tile[4*tx + 0][dr];
        o.y = tile[4*tx + 1][dr];
        o.z = tile[4*tx + 2][dr];
        o.w = tile[4*tx + 3][dr];
        *reinterpret_cast<float4*>(g_kvt + ((size_t)b * D_ + d0 + dr) * L_ + l0 + 4 * tx) = o;
    }
}

// -------- per-channel FFT convolution --------------------------------------
__global__ void __launch_bounds__(1024) conv_kernel(const float* __restrict__ bias){
    extern __shared__ float2 sm[];
    float2* a = sm;
    float2* b = sm + M_;
    const int c = blockIdx.x;                 // c = bidx*D + d
    const int d = c & (D_ - 1);
    const int g = d >> 3;                     // DG_ = 8
    const float bs = __ldg(bias + d);
    const float2* kv2 = reinterpret_cast<const float2*>(g_kvt + (size_t)c * L_);

    // forward: gmem-fused first pass + 3 broadcast-table smem passes
    pass_first_gmem(kv2, a);                      __syncthreads();
    pass_smem<-1, 3, true>(a, b, g_twp4 + OF3);   __syncthreads();
    pass_smem<-1, 6, true>(b, a, g_twp4 + OF6);   __syncthreads();
    pass_smem<-1, 9, true>(a, b, g_twp4 + OF9);   __syncthreads();

    // spectral: fwd r2 fold + Hermitian * (H+bias) + repack + inv r2 fold
    const float2* Hf = g_Hf + (size_t)g * HFS_;
    for (int k = threadIdx.x; k < 2048; k += 1024){
        if (k == 0){
            float2 A0 = b[0],    A1 = b[4096];
            float2 A2 = b[2048], A3 = b[6144];
            float2 Z0 = cadd(A0, A1), Z4 = csub(A0, A1);
            float2 Z2 = cadd(A2, A3), Z6 = csub(A2, A3);
            float X0 = Z0.x + Z0.y, X8 = Z0.x - Z0.y;
            float Y0 = X0 * (__ldg(&Hf[0].x)    + bs);
            float Y8 = X8 * (__ldg(&Hf[8192].x) + bs);
            float2 C0 = make_float2(0.5f*(Y0 + Y8), 0.5f*(Y0 - Y8));
            float2 X4 = make_float2(Z4.x, -Z4.y);
            float2 G4 = __ldg(&Hf[4096]); G4.x += bs;
            float2 Y4 = cmul(X4, G4);
            float2 C4 = make_float2(Y4.x, -Y4.y);
            float4 sc2 = __ldg(g_sp + 2048);     // (W2048, e^{+i*pi/2})
            float2 W2 = make_float2(sc2.x, sc2.y);
            float2 Xk, Xm;
            herm_unpack(Z2, Z6, W2, Xk, Xm);
            float2 Gk = __ldg(&Hf[2048]); Gk.x += bs;
            float2 Gm = __ldg(&Hf[6144]); Gm.x += bs;
            float2 C2, C6;
            herm_repack(cmul(Xk, Gk), cmul(Xm, Gm), W2, C2, C6);
            a[0] = cadd(C0, C4);
            a[1] = csub(C0, C4);
            float2 w = make_float2(sc2.z, sc2.w);
            a[4096] = cadd(C2, C6);
            a[4097] = cmul(w, csub(C2, C6));
        } else {
            const int k2 = 4096 - k;
            const int s1 = sw(k), s2 = sw(k2);
            float4 spk  = __ldg(g_sp + k);       // (Wk, wA)
            float4 spk2 = __ldg(g_sp + k2);      // (Wk2, wB)
            float2 Gk  = __ldg(&Hf[k]);        Gk.x  += bs;
            float2 Gm  = __ldg(&Hf[8192 - k]); Gm.x  += bs;
            float2 Gk2 = __ldg(&Hf[k2]);       Gk2.x += bs;
            float2 Gk4 = __ldg(&Hf[4096 + k]); Gk4.x += bs;
            float2 A0 = b[s1], A1 = b[s1 + 4096];
            float2 A2 = b[s2], A3 = b[s2 + 4096];
            float2 Zk  = cadd(A0, A1);
            float2 Zk4 = csub(A0, A1);
            float2 Zk2 = cadd(A2, A3);
            float2 Zm  = csub(A2, A3);
            float2 Wk  = make_float2(spk.x,  spk.y);
            float2 Wk2 = make_float2(spk2.x, spk2.y);
            float2 Xk, Xm, Xk2, Xk4;
            herm_unpack(Zk,  Zm,  Wk,  Xk,  Xm);
            herm_unpack(Zk2, Zk4, Wk2, Xk2, Xk4);
            float2 Ck, Cm, Ck2, Ck4;
            herm_repack(cmul(Xk,  Gk),  cmul(Xm,  Gm),  Wk,  Ck,  Cm);
            herm_repack(cmul(Xk2, Gk2), cmul(Xk4, Gk4), Wk2, Ck2, Ck4);
            // inverse radix-2 fold (s=1): p=k -> 2k,2k+1 ; p=k2 -> 2k2,2k2+1
            int o1 = sw(2 * k);
            float2 wA = make_float2(spk.z, spk.w);
            a[o1]     = cadd(Ck, Ck4);
            a[o1 ^ 1] = cmul(wA, csub(Ck, Ck4));
            int o2 = sw(2 * k2);
            float2 wB = make_float2(spk2.z, spk2.w);
            a[o2]     = cadd(Ck2, Cm);
            a[o2 ^ 1] = cmul(wB, csub(Ck2, Cm));
        }
    }
    __syncthreads();

    // inverse: LS=1 computed (distinct p), LS=4/7 broadcast tables, last fused
    pass_smem<+1, 1, false>(a, b, nullptr);       __syncthreads();
    pass_smem<+1, 4, true>(b, a, g_twp4 + OI4);   __syncthreads();
    pass_smem<+1, 7, true>(a, b, g_twp4 + OI7);   __syncthreads();
    float2* out2 = reinterpret_cast<float2*>(g_kvt + (size_t)c * L_);
    pass_last_inv_gmem(b, out2);
}

// -------- gate + transpose back: out(b,l,d) = x1(b,l,d) * y_t(b,d,l) -------
__global__ void gate_transpose(const float* __restrict__ x1,
                               float* __restrict__ out){
    __shared__ float tile[64][65];               // [l-local][d-local]
    const int b  = blockIdx.z;
    const int l0 = blockIdx.x * 64;
    const int d0 = blockIdx.y * 64;
    const int tx = threadIdx.x;                  // 0..15
    const int ty = threadIdx.y;                  // 0..15
    #pragma unroll
    for (int i = 0; i < 4; i++){
        int dr = ty + 16 * i;
        float4 ya = *reinterpret_cast<const float4*>(
            g_kvt + ((size_t)b * D_ + d0 + dr) * L_ + l0 + 4 * tx);
        tile[4*tx + 0][dr] = ya.x;
        tile[4*tx + 1][dr] = ya.y;
        tile[4*tx + 2][dr] = ya.z;
        tile[4*tx + 3][dr] = ya.w;
    }
    __syncthreads();
    #pragma unroll
    for (int i = 0; i < 4; i++){
        int lr = ty + 16 * i;
        size_t idx = ((size_t)b * L_ + (l0 + lr)) * D_ + d0 + 4 * tx;
        float4 xa = *reinterpret_cast<const float4*>(x1 + idx);
        float4 o;
        o.x = xa.x * tile[lr][4*tx + 0];
        o.y = xa.y * tile[lr][4*tx + 1];
        o.z = xa.z * tile[lr][4*tx + 2];
        o.w = xa.w * tile[lr][4*tx + 3];
        *reinterpret_cast<float4*>(out + idx) = o;
    }
}

// ---------------------------------------------------------------------------
extern "C" void kernel_launch(void* const* d_in, const int* in_sizes, int n_in,
                              void* d_out, int out_size){
    const float* x1   = (const float*)d_in[0];
    const float* x2   = (const float*)d_in[1];
    const float* v    = (const float*)d_in[2];
    const float* h    = (const float*)d_in[3];
    const float* bias = (const float*)d_in[4];
    float* out = (float*)d_out;

    const int SMEM = 2 * M_ * (int)sizeof(float2);   // 131072 B
    cudaFuncSetAttribute(hf_kernel,   cudaFuncAttributeMaxDynamicSharedMemorySize, SMEM);
    cudaFuncSetAttribute(conv_kernel, cudaFuncAttributeMaxDynamicSharedMemorySize, SMEM);

    tw_kernel<<<(M_ + 255) / 256, 256>>>();
    sp_kernel<<<16, 256>>>();
    twp_kernel<<<1, 256>>>();
    hf_kernel<<<G_, 1024, SMEM>>>(h);

    dim3 tgrid(L_ / 64, D_ / 64, B_);
    dim3 tblk(16, 16);
    pregate_transpose<<<tgrid, tblk>>>(x2, v);

    conv_kernel<<<B_ * D_, 1024, SMEM>>>(bias);

    gate_transpose<<<tgrid, tblk>>>(x1, out);
}

// round 11
// speedup vs baseline: 1.2650x; 1.1799x over previous
#include <cuda_runtime.h>
#include <math.h>

// Problem constants (fixed instance)
#define B_   2
#define L_   8192
#define G_   256
#define DG_  8
#define D_   2048          // G_*DG_
#define M_   8192          // complex FFT length (= L)
#define HFS_ 8208          // Hf row stride (>= 8193, 16B-multiple)

// -------- device scratch (static: no runtime allocation allowed) ----------
__device__ __align__(256) float  g_kvt[(size_t)B_ * D_ * L_];  // (B,D,L) kv then y
__device__ __align__(256) float2 g_Hf[(size_t)G_ * HFS_];      // rfft(h_g) bins 0..8192
__device__ __align__(256) float2 g_tw[M_];                     // e^{-2*pi*i*k/16384}

// smem bank swizzle: inject bits 4..7 into the bank field (bits 0..3).
__device__ __forceinline__ int sw(int c){ return c ^ ((c >> 4) & 0xF); }

// -------- complex helpers --------------------------------------------------
__device__ __forceinline__ float2 cadd(float2 a, float2 b){ return make_float2(a.x+b.x, a.y+b.y); }
__device__ __forceinline__ float2 csub(float2 a, float2 b){ return make_float2(a.x-b.x, a.y-b.y); }
__device__ __forceinline__ float2 cmul(float2 a, float2 b){
    return make_float2(a.x*b.x - a.y*b.y, a.x*b.y + a.y*b.x);
}
template<int DIR>
__device__ __forceinline__ float2 jmul(float2 z){
    return (DIR < 0) ? make_float2(z.y, -z.x) : make_float2(-z.y, z.x);
}

// -------- 8-point DFT (kernel e^{DIR*2*pi*i*r*j/8}) ------------------------
template<int DIR>
__device__ __forceinline__ void dft8(const float2 a[8], float2 B[8]){
    const float C = 0.70710678118654752f;
    float2 s0 = cadd(a[0], a[4]), s1 = csub(a[0], a[4]);
    float2 s2 = cadd(a[2], a[6]), s3 = csub(a[2], a[6]);
    float2 e0 = cadd(s0, s2),     e2 = csub(s0, s2);
    float2 js3 = jmul<DIR>(s3);
    float2 e1 = cadd(s1, js3),    e3 = csub(s1, js3);
    float2 u0 = cadd(a[1], a[5]), u1 = csub(a[1], a[5]);
    float2 u2 = cadd(a[3], a[7]), u3 = csub(a[3], a[7]);
    float2 o0 = cadd(u0, u2),     o2 = csub(u0, u2);
    float2 ju3 = jmul<DIR>(u3);
    float2 o1 = cadd(u1, ju3),    o3 = csub(u1, ju3);
    const float2 w1 = make_float2( C, (DIR < 0) ? -C : C);
    const float2 w3 = make_float2(-C, (DIR < 0) ? -C : C);
    float2 t1 = cmul(w1, o1);
    float2 t2 = jmul<DIR>(o2);
    float2 t3 = cmul(w3, o3);
    B[0] = cadd(e0, o0); B[4] = csub(e0, o0);
    B[1] = cadd(e1, t1); B[5] = csub(e1, t1);
    B[2] = cadd(e2, t2); B[6] = csub(e2, t2);
    B[3] = cadd(e3, t3); B[7] = csub(e3, t3);
}

// log-depth twiddle powers: w[r] = w1^r
__device__ __forceinline__ void twpowers(float2 w1, float2 w[8]){
    w[1] = w1;
    w[2] = cmul(w1, w1);
    w[3] = cmul(w1, w[2]);
    w[4] = cmul(w[2], w[2]);
    w[5] = cmul(w[2], w[3]);
    w[6] = cmul(w[3], w[3]);
    w[7] = cmul(w[3], w[4]);
}

// -------- first forward pass: gmem -> smem, LS=0, upper half zero ----------
// 512 threads, 2 butterflies each; write-only into smem (caller syncs after)
__device__ __forceinline__ void pass_first_g512(const float2* __restrict__ g,
                                                float2* __restrict__ y){
    #pragma unroll
    for (int it = 0; it < 2; it++){
        const int t = threadIdx.x + 512 * it;
        float2 a[8];
        #pragma unroll
        for (int j = 0; j < 4; j++) a[j] = __ldg(g + t + 1024 * j);
        #pragma unroll
        for (int j = 4; j < 8; j++) a[j] = make_float2(0.f, 0.f);
        float2 Bv[8];
        dft8<-1>(a, Bv);
        float2 w[8];
        twpowers(g_tw[t << 1], w);
        const int base = t << 3;
        const int m = (base >> 4) & 0xF;       // constant across r<8; XOR per index
        y[base ^ m] = Bv[0];
        #pragma unroll
        for (int r = 1; r < 8; r++) y[(base + r) ^ m] = cmul(w[r], Bv[r]);
    }
}

// -------- in-place mid radix-8 pass (single smem buffer), s = 1<<LS --------
// 512 threads, 2 butterflies each. Read-all -> sync -> write-all -> sync.
template<int DIR, int LS>
__device__ __forceinline__ void pass_ip(float2* __restrict__ x){
    const int t0 = threadIdx.x;
    const int t1 = threadIdx.x + 512;
    float2 a0[8], a1[8];
    const int xs0 = sw(t0), xs1 = sw(t1);      // sw(t+1024j) = sw(t)+1024j
    #pragma unroll
    for (int j = 0; j < 8; j++) a0[j] = x[xs0 + 1024 * j];
    #pragma unroll
    for (int j = 0; j < 8; j++) a1[j] = x[xs1 + 1024 * j];
    __syncthreads();
    {
        const int q = t0 & ((1 << LS) - 1);
        const int p = t0 >> LS;
        float2 w1 = g_tw[p << (LS + 1)];
        if (DIR > 0) w1.y = -w1.y;
        float2 w[8]; twpowers(w1, w);
        float2 Bv[8];
        dft8<DIR>(a0, Bv);
        const int base = q + (p << (LS + 3));
        if constexpr (LS >= 8){
            const int sb = sw(base);           // r<<LS disjoint from swizzle bits
            x[sb] = Bv[0];
            #pragma unroll
            for (int r = 1; r < 8; r++) x[sb + (r << LS)] = cmul(w[r], Bv[r]);
        } else {
            x[sw(base)] = Bv[0];
            #pragma unroll
            for (int r = 1; r < 8; r++) x[sw(base + (r << LS))] = cmul(w[r], Bv[r]);
        }
    }
    {
        const int q = t1 & ((1 << LS) - 1);
        const int p = t1 >> LS;
        float2 w1 = g_tw[p << (LS + 1)];
        if (DIR > 0) w1.y = -w1.y;
        float2 w[8]; twpowers(w1, w);
        float2 Bv[8];
        dft8<DIR>(a1, Bv);
        const int base = q + (p << (LS + 3));
        if constexpr (LS >= 8){
            const int sb = sw(base);
            x[sb] = Bv[0];
            #pragma unroll
            for (int r = 1; r < 8; r++) x[sb + (r << LS)] = cmul(w[r], Bv[r]);
        } else {
            x[sw(base)] = Bv[0];
            #pragma unroll
            for (int r = 1; r < 8; r++) x[sw(base + (r << LS))] = cmul(w[r], Bv[r]);
        }
    }
    __syncthreads();
}

// -------- last inverse pass: smem -> gmem, s=1024 => p=0 => unit twiddles --
// only n = t + 1024r < 4096 (r<4) needed (packed-real output); 1/8192 folded
__device__ __forceinline__ void pass_last_g512(const float2* __restrict__ x,
                                               float2* __restrict__ g){
    #pragma unroll
    for (int it = 0; it < 2; it++){
        const int t  = threadIdx.x + 512 * it;
        const int xs = sw(t);
        float2 a[8];
        #pragma unroll
        for (int j = 0; j < 8; j++) a[j] = x[xs + 1024 * j];
        float2 Bv[8];
        dft8<+1>(a, Bv);
        const float sc = 1.0f / 8192.0f;
        #pragma unroll
        for (int r = 0; r < 4; r++)
            g[t + 1024 * r] = make_float2(Bv[r].x * sc, Bv[r].y * sc);
    }
}

// -------- Hermitian unpack/repack helpers (packed-real trick) ---------------
__device__ __forceinline__ void herm_unpack(float2 Zk, float2 Zm, float2 Wk,
                                            float2& Xk, float2& Xm){
    float2 Ze = make_float2(0.5f*(Zk.x + Zm.x), 0.5f*(Zk.y - Zm.y));
    float2 Zo = make_float2(0.5f*(Zk.y + Zm.y), -0.5f*(Zk.x - Zm.x));
    float2 WZo = cmul(Wk, Zo);
    Xk = cadd(Ze, WZo);
    Xm = csub(Ze, WZo); Xm.y = -Xm.y;          // conj
}
__device__ __forceinline__ void herm_repack(float2 Yk, float2 Ym, float2 Wk,
                                            float2& Ck, float2& Cm){
    float2 Ze2 = make_float2(0.5f*(Yk.x + Ym.x), 0.5f*(Yk.y - Ym.y));
    float2 T   = make_float2(0.5f*(Yk.x - Ym.x), 0.5f*(Yk.y + Ym.y));
    float2 Wc  = make_float2(Wk.x, -Wk.y);
    float2 Zo2 = cmul(Wc, T);
    Ck = make_float2(Ze2.x - Zo2.y,  Ze2.y + Zo2.x);
    Cm = make_float2(Ze2.x + Zo2.y, -Ze2.y + Zo2.x);
}

// -------- twiddle table ----------------------------------------------------
__global__ void tw_kernel(){
    int k = blockIdx.x * 256 + threadIdx.x;
    if (k < M_){
        double s, c;
        sincospi(-(double)k / 8192.0, &s, &c);   // -2*pi*k/16384
        g_tw[k] = make_float2((float)c, (float)s);
    }
}

// -------- Hf = rfft(h_g, 16384), bins 0..8192 ------------------------------
__global__ void __launch_bounds__(512, 2) hf_kernel(const float* __restrict__ h){
    extern __shared__ float2 sm[];
    float2* a = sm;
    const int g = blockIdx.x;
    const float2* h2 = reinterpret_cast<const float2*>(h + (size_t)g * L_);

    pass_first_g512(h2, a);  __syncthreads();
    pass_ip<-1, 3>(a);
    pass_ip<-1, 6>(a);
    pass_ip<-1, 9>(a);
    // a holds A ; Z[t] = A[t] + A[t+4096], Z[t+4096] = A[t] - A[t+4096]
    // read-only tail -> gmem, no further syncs needed
    float2* Hf = g_Hf + (size_t)g * HFS_;
    #pragma unroll
    for (int i = 0; i < 4; i++){
        int k = threadIdx.x + 512 * i;
        if (k == 0){
            float2 A0 = a[0],    A1 = a[4096];
            float2 A2 = a[2048], A3 = a[6144];   // sw() identity here
            float2 Z0 = cadd(A0, A1), Z4 = csub(A0, A1);
            float2 Z2 = cadd(A2, A3), Z6 = csub(A2, A3);
            Hf[0]    = make_float2(Z0.x + Z0.y, 0.f);
            Hf[8192] = make_float2(Z0.x - Z0.y, 0.f);
            Hf[4096] = make_float2(Z4.x, -Z4.y);
            float2 Xk, Xm;
            herm_unpack(Z2, Z6, g_tw[2048], Xk, Xm);
            Hf[2048] = Xk; Hf[6144] = Xm;
        } else {
            const int k2 = 4096 - k;
            const int s1 = sw(k), s2 = sw(k2);   // sw(t+4096) = sw(t)+4096
            float2 A0 = a[s1], A1 = a[s1 + 4096];
            float2 A2 = a[s2], A3 = a[s2 + 4096];
            float2 Zk  = cadd(A0, A1);
            float2 Zk4 = csub(A0, A1);
            float2 Zk2 = cadd(A2, A3);
            float2 Zm  = csub(A2, A3);
            float2 Xk, Xm, Xk2, Xk4;
            herm_unpack(Zk,  Zm,  g_tw[k],  Xk,  Xm);
            herm_unpack(Zk2, Zk4, g_tw[k2], Xk2, Xk4);
            Hf[k] = Xk;   Hf[8192 - k] = Xm;
            Hf[k2] = Xk2; Hf[4096 + k] = Xk4;
        }
    }
}

// -------- pregate + transpose: kv_t(b,d,l) = x2(b,l,d)*v(b,l,d) ------------
// 64x64 tiles, block (16,16): 4 float4 in flight per thread per phase
__global__ void pregate_transpose(const float* __restrict__ x2,
                                  const float* __restrict__ v){
    __shared__ float tile[64][65];               // [l-local][d-local]
    const int b  = blockIdx.z;
    const int l0 = blockIdx.x * 64;
    const int d0 = blockIdx.y * 64;
    const int tx = threadIdx.x;                  // 0..15
    const int ty = threadIdx.y;                  // 0..15
    #pragma unroll
    for (int i = 0; i < 4; i++){
        int lr = ty + 16 * i;
        size_t idx = ((size_t)b * L_ + (l0 + lr)) * D_ + d0 + 4 * tx;
        float4 xa = *reinterpret_cast<const float4*>(x2 + idx);
        float4 va = *reinterpret_cast<const float4*>(v  + idx);
        tile[lr][4*tx + 0] = xa.x * va.x;
        tile[lr][4*tx + 1] = xa.y * va.y;
        tile[lr][4*tx + 2] = xa.z * va.z;
        tile[lr][4*tx + 3] = xa.w * va.w;
    }
    __syncthreads();
    #pragma unroll
    for (int i = 0; i < 4; i++){
        int dr = ty + 16 * i;
        float4 o;
        o.x = tile[4*tx + 0][dr];
        o.y = tile[4*tx + 1][dr];
        o.z = tile[4*tx + 2][dr];
        o.w = tile[4*tx + 3][dr];
        *reinterpret_cast<float4*>(g_kvt + ((size_t)b * D_ + d0 + dr) * L_ + l0 + 4 * tx) = o;
    }
}

// -------- per-channel FFT convolution (in-place, 64KB smem, 2 CTAs/SM) -----
__global__ void __launch_bounds__(512, 2) conv_kernel(const float* __restrict__ bias){
    extern __shared__ float2 sm[];
    float2* a = sm;
    const int c = blockIdx.x;                 // c = bidx*D + d
    const int d = c & (D_ - 1);
    const int g = d >> 3;                     // DG_ = 8
    const float bs = __ldg(bias + d);
    const float2* kv2 = reinterpret_cast<const float2*>(g_kvt + (size_t)c * L_);

    // forward: gmem-fused first pass + 3 in-place passes
    pass_first_g512(kv2, a);  __syncthreads();
    pass_ip<-1, 3>(a);
    pass_ip<-1, 6>(a);
    pass_ip<-1, 9>(a);

    // spectral: fwd r2 fold + Hermitian * (H+bias) + repack + inv r2 fold.
    // In-place: read ALL quads first, sync, then compute + write, sync.
    const float2* Hf = g_Hf + (size_t)g * HFS_;
    float2 A[4][4];
    #pragma unroll
    for (int i = 0; i < 4; i++){
        int k = threadIdx.x + 512 * i;
        if (k == 0){
            A[i][0] = a[0]; A[i][1] = a[4096]; A[i][2] = a[2048]; A[i][3] = a[6144];
        } else {
            int k2 = 4096 - k;
            int s1 = sw(k), s2 = sw(k2);
            A[i][0] = a[s1]; A[i][1] = a[s1 + 4096];
            A[i][2] = a[s2]; A[i][3] = a[s2 + 4096];
        }
    }
    __syncthreads();
    #pragma unroll
    for (int i = 0; i < 4; i++){
        int k = threadIdx.x + 512 * i;
        if (k == 0){
            float2 Z0 = cadd(A[i][0], A[i][1]), Z4 = csub(A[i][0], A[i][1]);
            float2 Z2 = cadd(A[i][2], A[i][3]), Z6 = csub(A[i][2], A[i][3]);
            float X0 = Z0.x + Z0.y, X8 = Z0.x - Z0.y;
            float Y0 = X0 * (__ldg(&Hf[0].x)    + bs);
            float Y8 = X8 * (__ldg(&Hf[8192].x) + bs);
            float2 C0 = make_float2(0.5f*(Y0 + Y8), 0.5f*(Y0 - Y8));
            float2 X4 = make_float2(Z4.x, -Z4.y);
            float2 G4 = __ldg(&Hf[4096]); G4.x += bs;
            float2 Y4 = cmul(X4, G4);
            float2 C4 = make_float2(Y4.x, -Y4.y);
            float2 W2 = g_tw[2048];
            float2 Xk, Xm;
            herm_unpack(Z2, Z6, W2, Xk, Xm);
            float2 Gk = __ldg(&Hf[2048]); Gk.x += bs;
            float2 Gm = __ldg(&Hf[6144]); Gm.x += bs;
            float2 C2, C6;
            herm_repack(cmul(Xk, Gk), cmul(Xm, Gm), W2, C2, C6);
            a[0] = cadd(C0, C4);
            a[1] = csub(C0, C4);                          // w^0 = 1
            float2 w = g_tw[4096]; w.y = -w.y;            // e^{+i*pi/2}
            a[4096] = cadd(C2, C6);                       // sw identity here
            a[4097] = cmul(w, csub(C2, C6));
        } else {
            const int k2 = 4096 - k;
            float2 Zk  = cadd(A[i][0], A[i][1]);    // Z[k]
            float2 Zk4 = csub(A[i][0], A[i][1]);    // Z[4096+k]
            float2 Zk2 = cadd(A[i][2], A[i][3]);    // Z[4096-k]
            float2 Zm  = csub(A[i][2], A[i][3]);    // Z[8192-k]
            float2 Wk = g_tw[k], Wk2 = g_tw[k2];
            float2 Xk, Xm, Xk2, Xk4;
            herm_unpack(Zk,  Zm,  Wk,  Xk,  Xm);    // bins k, 8192-k
            herm_unpack(Zk2, Zk4, Wk2, Xk2, Xk4);   // bins 4096-k, 4096+k
            float2 Gk  = __ldg(&Hf[k]);        Gk.x  += bs;
            float2 Gm  = __ldg(&Hf[8192 - k]); Gm.x  += bs;
            float2 Gk2 = __ldg(&Hf[k2]);       Gk2.x += bs;
            float2 Gk4 = __ldg(&Hf[4096 + k]); Gk4.x += bs;
            float2 Ck, Cm, Ck2, Ck4;
            herm_repack(cmul(Xk,  Gk),  cmul(Xm,  Gm),  Wk,  Ck,  Cm);
            herm_repack(cmul(Xk2, Gk2), cmul(Xk4, Gk4), Wk2, Ck2, Ck4);
            // inverse radix-2 fold (s=1): p=k -> 2k,2k+1 ; p=k2 -> 2k2,2k2+1
            int o1 = sw(2 * k);                           // sw(2k+1) = sw(2k)^1
            float2 wA = g_tw[2 * k];  wA.y = -wA.y;       // e^{+2*pi*i*k/8192}
            a[o1]     = cadd(Ck, Ck4);
            a[o1 ^ 1] = cmul(wA, csub(Ck, Ck4));
            int o2 = sw(2 * k2);
            float2 wB = g_tw[2 * k2]; wB.y = -wB.y;
            a[o2]     = cadd(Ck2, Cm);
            a[o2 ^ 1] = cmul(wB, csub(Ck2, Cm));
        }
    }
    __syncthreads();

    // inverse: 3 in-place passes + final pass fused with gmem store (r<4 only)
    pass_ip<+1, 1>(a);
    pass_ip<+1, 4>(a);
    pass_ip<+1, 7>(a);
    float2* out2 = reinterpret_cast<float2*>(g_kvt + (size_t)c * L_);
    pass_last_g512(a, out2);
}

// -------- gate + transpose back: out(b,l,d) = x1(b,l,d) * y_t(b,d,l) -------
__global__ void gate_transpose(const float* __restrict__ x1,
                               float* __restrict__ out){
    __shared__ float tile[64][65];               // [l-local][d-local]
    const int b  = blockIdx.z;
    const int l0 = blockIdx.x * 64;
    const int d0 = blockIdx.y * 64;
    const int tx = threadIdx.x;                  // 0..15
    const int ty = threadIdx.y;                  // 0..15
    #pragma unroll
    for (int i = 0; i < 4; i++){
        int dr = ty + 16 * i;
        float4 ya = *reinterpret_cast<const float4*>(
            g_kvt + ((size_t)b * D_ + d0 + dr) * L_ + l0 + 4 * tx);
        tile[4*tx + 0][dr] = ya.x;
        tile[4*tx + 1][dr] = ya.y;
        tile[4*tx + 2][dr] = ya.z;
        tile[4*tx + 3][dr] = ya.w;
    }
    __syncthreads();
    #pragma unroll
    for (int i = 0; i < 4; i++){
        int lr = ty + 16 * i;
        size_t idx = ((size_t)b * L_ + (l0 + lr)) * D_ + d0 + 4 * tx;
        float4 xa = *reinterpret_cast<const float4*>(x1 + idx);
        float4 o;
        o.x = xa.x * tile[lr][4*tx + 0];
        o.y = xa.y * tile[lr][4*tx + 1];
        o.z = xa.z * tile[lr][4*tx + 2];
        o.w = xa.w * tile[lr][4*tx + 3];
        *reinterpret_cast<float4*>(out + idx) = o;
    }
}

// ---------------------------------------------------------------------------
extern "C" void kernel_launch(void* const* d_in, const int* in_sizes, int n_in,
                              void* d_out, int out_size){
    const float* x1   = (const float*)d_in[0];
    const float* x2   = (const float*)d_in[1];
    const float* v    = (const float*)d_in[2];
    const float* h    = (const float*)d_in[3];
    const float* bias = (const float*)d_in[4];
    float* out = (float*)d_out;

    const int SMEM = M_ * (int)sizeof(float2);   // 65536 B (single buffer)
    cudaFuncSetAttribute(hf_kernel,   cudaFuncAttributeMaxDynamicSharedMemorySize, SMEM);
    cudaFuncSetAttribute(conv_kernel, cudaFuncAttributeMaxDynamicSharedMemorySize, SMEM);

    tw_kernel<<<(M_ + 255) / 256, 256>>>();
    hf_kernel<<<G_, 512, SMEM>>>(h);

    dim3 tgrid(L_ / 64, D_ / 64, B_);
    dim3 tblk(16, 16);
    pregate_transpose<<<tgrid, tblk>>>(x2, v);

    conv_kernel<<<B_ * D_, 512, SMEM>>>(bias);

    gate_transpose<<<tgrid, tblk>>>(x1, out);
}

// round 13
// speedup vs baseline: 1.3829x; 1.0932x over previous
#include <cuda_runtime.h>
#include <math.h>

// Problem constants (fixed instance)
#define B_   2
#define L_   8192
#define G_   256
#define DG_  8
#define D_   2048          // G_*DG_
#define M_   8192          // complex FFT length (= L)
#define HFS_ 8208          // Hf row stride (>= 8193, 16B-multiple)

// -------- device scratch (static: no runtime allocation allowed) ----------
__device__ __align__(256) float  g_kvt[(size_t)B_ * D_ * L_];  // (B,D,L) kv then y
__device__ __align__(256) float2 g_Hf[(size_t)G_ * HFS_];      // rfft(h_g) bins 0..8192
__device__ __align__(256) float2 g_tw[M_];                     // e^{-2*pi*i*k/16384}

// pair-space smem swizzle: P = complex_index/2 ; element parity is preserved,
// so a float4 (= complex pair {2P, 2P+1}) stays contiguous after swizzling.
__device__ __forceinline__ int swp(int P){ return P ^ ((P >> 3) & 7); }
// scalar float2 slot for complex index c
__device__ __forceinline__ int at(int c){ return 2 * swp(c >> 1) + (c & 1); }

// -------- complex helpers --------------------------------------------------
__device__ __forceinline__ float2 cadd(float2 a, float2 b){ return make_float2(a.x+b.x, a.y+b.y); }
__device__ __forceinline__ float2 csub(float2 a, float2 b){ return make_float2(a.x-b.x, a.y-b.y); }
__device__ __forceinline__ float2 cmul(float2 a, float2 b){
    return make_float2(a.x*b.x - a.y*b.y, a.x*b.y + a.y*b.x);
}
template<int DIR>
__device__ __forceinline__ float2 jmul(float2 z){
    return (DIR < 0) ? make_float2(z.y, -z.x) : make_float2(-z.y, z.x);
}

// -------- 8-point DFT (kernel e^{DIR*2*pi*i*r*j/8}) ------------------------
template<int DIR>
__device__ __forceinline__ void dft8(const float2 a[8], float2 B[8]){
    const float C = 0.70710678118654752f;
    float2 s0 = cadd(a[0], a[4]), s1 = csub(a[0], a[4]);
    float2 s2 = cadd(a[2], a[6]), s3 = csub(a[2], a[6]);
    float2 e0 = cadd(s0, s2),     e2 = csub(s0, s2);
    float2 js3 = jmul<DIR>(s3);
    float2 e1 = cadd(s1, js3),    e3 = csub(s1, js3);
    float2 u0 = cadd(a[1], a[5]), u1 = csub(a[1], a[5]);
    float2 u2 = cadd(a[3], a[7]), u3 = csub(a[3], a[7]);
    float2 o0 = cadd(u0, u2),     o2 = csub(u0, u2);
    float2 ju3 = jmul<DIR>(u3);
    float2 o1 = cadd(u1, ju3),    o3 = csub(u1, ju3);
    const float2 w1 = make_float2( C, (DIR < 0) ? -C : C);
    const float2 w3 = make_float2(-C, (DIR < 0) ? -C : C);
    float2 t1 = cmul(w1, o1);
    float2 t2 = jmul<DIR>(o2);
    float2 t3 = cmul(w3, o3);
    B[0] = cadd(e0, o0); B[4] = csub(e0, o0);
    B[1] = cadd(e1, t1); B[5] = csub(e1, t1);
    B[2] = cadd(e2, t2); B[6] = csub(e2, t2);
    B[3] = cadd(e3, t3); B[7] = csub(e3, t3);
}

// log-depth twiddle powers: w[r] = w1^r
__device__ __forceinline__ void twpowers(float2 w1, float2 w[8]){
    w[1] = w1;
    w[2] = cmul(w1, w1);
    w[3] = cmul(w1, w[2]);
    w[4] = cmul(w[2], w[2]);
    w[5] = cmul(w[2], w[3]);
    w[6] = cmul(w[3], w[3]);
    w[7] = cmul(w[3], w[4]);
}

// -------- first forward pass: gmem -> smem, radix-8 s=1, upper half zero ---
// thread t handles butterflies b = 2t and 2t+1 (adjacent gmem/smem pairs)
__device__ __forceinline__ void pass_first_g512(const float4* __restrict__ g4,
                                                float4* __restrict__ y4){
    const int t = threadIdx.x;
    float2 a0[8], a1[8];
    #pragma unroll
    for (int j = 0; j < 4; j++){
        float4 v = __ldg(g4 + t + 512 * j);
        a0[j] = make_float2(v.x, v.y);
        a1[j] = make_float2(v.z, v.w);
    }
    #pragma unroll
    for (int j = 4; j < 8; j++){ a0[j] = make_float2(0.f,0.f); a1[j] = make_float2(0.f,0.f); }
    float2 B0[8], B1[8];
    dft8<-1>(a0, B0);
    dft8<-1>(a1, B1);
    float2 wA[8], wB[8];
    twpowers(g_tw[4*t],     wA);      // p = 2t
    twpowers(g_tw[4*t + 2], wB);      // p = 2t+1
    float2 cA[8], cB[8];
    cA[0] = B0[0]; cB[0] = B1[0];
    #pragma unroll
    for (int r = 1; r < 8; r++){ cA[r] = cmul(wA[r], B0[r]); cB[r] = cmul(wB[r], B1[r]); }
    // outputs: butterfly A -> complex 16t+r (pairs P=8t+i), B -> 16t+8+r (pairs P=8t+4+i)
    const int m = t & 7;
    const int b8 = 8 * t;
    #pragma unroll
    for (int i = 0; i < 4; i++){
        y4[b8 + (i ^ m)]       = make_float4(cA[2*i].x, cA[2*i].y, cA[2*i+1].x, cA[2*i+1].y);
        y4[b8 + ((i + 4) ^ m)] = make_float4(cB[2*i].x, cB[2*i].y, cB[2*i+1].x, cB[2*i+1].y);
    }
}

// -------- in-place mid radix-8 pass (single buffer), s = 1<<LS, LS>=1 ------
// thread t: butterflies 2t, 2t+1 share p -> one twiddle set; float4 smem I/O
template<int DIR, int LS>
__device__ __forceinline__ void pass_ip2(float4* __restrict__ x4){
    const int t  = threadIdx.x;
    const int rb = swp(t);                     // swp(t+512j) = swp(t)+512j
    float2 a0[8], a1[8];
    #pragma unroll
    for (int j = 0; j < 8; j++){
        float4 v = x4[rb + 512 * j];
        a0[j] = make_float2(v.x, v.y);
        a1[j] = make_float2(v.z, v.w);
    }
    __syncthreads();
    const int p  = t >> (LS - 1);
    const int qh = t & ((1 << (LS - 1)) - 1);  // q/2
    float2 w1 = g_tw[p << (LS + 1)];
    if (DIR > 0) w1.y = -w1.y;
    float2 w[8]; twpowers(w1, w);
    float2 B0[8], B1[8];
    dft8<DIR>(a0, B0);
    dft8<DIR>(a1, B1);
    const int Pb = qh + (p << (LS + 2));       // base/2
    x4[swp(Pb)] = make_float4(B0[0].x, B0[0].y, B1[0].x, B1[0].y);
    #pragma unroll
    for (int r = 1; r < 8; r++){
        float2 c0 = cmul(w[r], B0[r]);
        float2 c1 = cmul(w[r], B1[r]);
        x4[swp(Pb + (r << (LS - 1)))] = make_float4(c0.x, c0.y, c1.x, c1.y);
    }
    __syncthreads();
}

// -------- last inverse pass: smem -> gmem, p=0 => unit twiddles ------------
// outputs n = 2t+1024r (A), 2t+1+1024r (B); only n<4096 kept (r<4); 1/8192
__device__ __forceinline__ void pass_last_g512(const float4* __restrict__ x4,
                                               float4* __restrict__ g4){
    const int t  = threadIdx.x;
    const int rb = swp(t);
    float2 a0[8], a1[8];
    #pragma unroll
    for (int j = 0; j < 8; j++){
        float4 v = x4[rb + 512 * j];
        a0[j] = make_float2(v.x, v.y);
        a1[j] = make_float2(v.z, v.w);
    }
    float2 B0[8], B1[8];
    dft8<+1>(a0, B0);
    dft8<+1>(a1, B1);
    const float sc = 1.0f / 8192.0f;
    #pragma unroll
    for (int r = 0; r < 4; r++)
        g4[t + 512 * r] = make_float4(B0[r].x * sc, B0[r].y * sc,
                                      B1[r].x * sc, B1[r].y * sc);
}

// -------- Hermitian unpack/repack helpers (packed-real trick) ---------------
__device__ __forceinline__ void herm_unpack(float2 Zk, float2 Zm, float2 Wk,
                                            float2& Xk, float2& Xm){
    float2 Ze = make_float2(0.5f*(Zk.x + Zm.x), 0.5f*(Zk.y - Zm.y));
    float2 Zo = make_float2(0.5f*(Zk.y + Zm.y), -0.5f*(Zk.x - Zm.x));
    float2 WZo = cmul(Wk, Zo);
    Xk = cadd(Ze, WZo);
    Xm = csub(Ze, WZo); Xm.y = -Xm.y;          // conj
}
__device__ __forceinline__ void herm_repack(float2 Yk, float2 Ym, float2 Wk,
                                            float2& Ck, float2& Cm){
    float2 Ze2 = make_float2(0.5f*(Yk.x + Ym.x), 0.5f*(Yk.y - Ym.y));
    float2 T   = make_float2(0.5f*(Yk.x - Ym.x), 0.5f*(Yk.y + Ym.y));
    float2 Wc  = make_float2(Wk.x, -Wk.y);
    float2 Zo2 = cmul(Wc, T);
    Ck = make_float2(Ze2.x - Zo2.y,  Ze2.y + Zo2.x);
    Cm = make_float2(Ze2.x + Zo2.y, -Ze2.y + Zo2.x);
}

// -------- twiddle table ----------------------------------------------------
__global__ void tw_kernel(){
    int k = blockIdx.x * 256 + threadIdx.x;
    if (k < M_){
        double s, c;
        sincospi(-(double)k / 8192.0, &s, &c);   // -2*pi*k/16384
        g_tw[k] = make_float2((float)c, (float)s);
    }
}

// -------- Hf = rfft(h_g, 16384), bins 0..8192 ------------------------------
__global__ void __launch_bounds__(512, 2) hf_kernel(const float* __restrict__ h){
    extern __shared__ float2 sm[];
    float4* s4 = reinterpret_cast<float4*>(sm);
    const int g = blockIdx.x;
    const float4* h4 = reinterpret_cast<const float4*>(h + (size_t)g * L_);

    pass_first_g512(h4, s4);  __syncthreads();
    pass_ip2<-1, 3>(s4);
    pass_ip2<-1, 6>(s4);
    pass_ip2<-1, 9>(s4);
    // sm holds A ; Z[t] = A[t] + A[t+4096], Z[t+4096] = A[t] - A[t+4096]
    float2* Hf = g_Hf + (size_t)g * HFS_;
    #pragma unroll
    for (int i = 0; i < 4; i++){
        int k = threadIdx.x + 512 * i;
        if (k == 0){
            float2 A0 = sm[at(0)],    A1 = sm[at(4096)];
            float2 A2 = sm[at(2048)], A3 = sm[at(6144)];
            float2 Z0 = cadd(A0, A1), Z4 = csub(A0, A1);
            float2 Z2 = cadd(A2, A3), Z6 = csub(A2, A3);
            Hf[0]    = make_float2(Z0.x + Z0.y, 0.f);
            Hf[8192] = make_float2(Z0.x - Z0.y, 0.f);
            Hf[4096] = make_float2(Z4.x, -Z4.y);
            float2 Xk, Xm;
            herm_unpack(Z2, Z6, g_tw[2048], Xk, Xm);
            Hf[2048] = Xk; Hf[6144] = Xm;
        } else {
            const int k2 = 4096 - k;
            const int s1 = at(k), s2 = at(k2);   // at(c+4096) = at(c)+4096
            float2 A0 = sm[s1], A1 = sm[s1 + 4096];
            float2 A2 = sm[s2], A3 = sm[s2 + 4096];
            float2 Zk  = cadd(A0, A1);
            float2 Zk4 = csub(A0, A1);
            float2 Zk2 = cadd(A2, A3);
            float2 Zm  = csub(A2, A3);
            float2 Xk, Xm, Xk2, Xk4;
            herm_unpack(Zk,  Zm,  g_tw[k],  Xk,  Xm);
            herm_unpack(Zk2, Zk4, g_tw[k2], Xk2, Xk4);
            Hf[k] = Xk;   Hf[8192 - k] = Xm;
            Hf[k2] = Xk2; Hf[4096 + k] = Xk4;
        }
    }
}

// -------- pregate + transpose: kv_t(b,d,l) = x2(b,l,d)*v(b,l,d) ------------
__global__ void pregate_transpose(const float* __restrict__ x2,
                                  const float* __restrict__ v){
    __shared__ float tile[64][65];               // [l-local][d-local]
    const int b  = blockIdx.z;
    const int l0 = blockIdx.x * 64;
    const int d0 = blockIdx.y * 64;
    const int tx = threadIdx.x;                  // 0..15
    const int ty = threadIdx.y;                  // 0..15
    #pragma unroll
    for (int i = 0; i < 4; i++){
        int lr = ty + 16 * i;
        size_t idx = ((size_t)b * L_ + (l0 + lr)) * D_ + d0 + 4 * tx;
        float4 xa = *reinterpret_cast<const float4*>(x2 + idx);
        float4 va = *reinterpret_cast<const float4*>(v  + idx);
        tile[lr][4*tx + 0] = xa.x * va.x;
        tile[lr][4*tx + 1] = xa.y * va.y;
        tile[lr][4*tx + 2] = xa.z * va.z;
        tile[lr][4*tx + 3] = xa.w * va.w;
    }
    __syncthreads();
    #pragma unroll
    for (int i = 0; i < 4; i++){
        int dr = ty + 16 * i;
        float4 o;
        o.x = tile[4*tx + 0][dr];
        o.y = tile[4*tx + 1][dr];
        o.z = tile[4*tx + 2][dr];
        o.w = tile[4*tx + 3][dr];
        *reinterpret_cast<float4*>(g_kvt + ((size_t)b * D_ + d0 + dr) * L_ + l0 + 4 * tx) = o;
    }
}

// -------- per-channel FFT convolution (in-place, 64KB smem, 2 CTAs/SM) -----
__global__ void __launch_bounds__(512, 2) conv_kernel(const float* __restrict__ bias){
    extern __shared__ float2 sm[];
    float4* s4 = reinterpret_cast<float4*>(sm);
    const int c = blockIdx.x;                 // c = bidx*D + d
    const int d = c & (D_ - 1);
    const int g = d >> 3;                     // DG_ = 8
    const float bs = __ldg(bias + d);
    const float4* kv4 = reinterpret_cast<const float4*>(g_kvt + (size_t)c * L_);

    // forward: gmem-fused first pass + 3 in-place passes
    pass_first_g512(kv4, s4);  __syncthreads();
    pass_ip2<-1, 3>(s4);
    pass_ip2<-1, 6>(s4);
    pass_ip2<-1, 9>(s4);

    // spectral: fwd r2 fold + Hermitian * (H+bias) + repack + inv r2 fold.
    // In-place: read ALL quads first, sync, then compute + float4 writes, sync.
    const float2* Hf = g_Hf + (size_t)g * HFS_;
    float2 A[4][4];
    #pragma unroll
    for (int i = 0; i < 4; i++){
        int k = threadIdx.x + 512 * i;
        if (k == 0){
            A[i][0] = sm[at(0)];    A[i][1] = sm[at(4096)];
            A[i][2] = sm[at(2048)]; A[i][3] = sm[at(6144)];
        } else {
            int k2 = 4096 - k;
            int s1 = at(k), s2 = at(k2);
            A[i][0] = sm[s1]; A[i][1] = sm[s1 + 4096];
            A[i][2] = sm[s2]; A[i][3] = sm[s2 + 4096];
        }
    }
    __syncthreads();
    #pragma unroll
    for (int i = 0; i < 4; i++){
        int k = threadIdx.x + 512 * i;
        if (k == 0){
            float2 Z0 = cadd(A[i][0], A[i][1]), Z4 = csub(A[i][0], A[i][1]);
            float2 Z2 = cadd(A[i][2], A[i][3]), Z6 = csub(A[i][2], A[i][3]);
            float X0 = Z0.x + Z0.y, X8 = Z0.x - Z0.y;
            float Y0 = X0 * (__ldg(&Hf[0].x)    + bs);
            float Y8 = X8 * (__ldg(&Hf[8192].x) + bs);
            float2 C0 = make_float2(0.5f*(Y0 + Y8), 0.5f*(Y0 - Y8));
            float2 X4 = make_float2(Z4.x, -Z4.y);
            float2 G4 = __ldg(&Hf[4096]); G4.x += bs;
            float2 Y4 = cmul(X4, G4);
            float2 C4 = make_float2(Y4.x, -Y4.y);
            float2 W2 = g_tw[2048];
            float2 Xk, Xm;
            herm_unpack(Z2, Z6, W2, Xk, Xm);
            float2 Gk = __ldg(&Hf[2048]); Gk.x += bs;
            float2 Gm = __ldg(&Hf[6144]); Gm.x += bs;
            float2 C2, C6;
            herm_repack(cmul(Xk, Gk), cmul(Xm, Gm), W2, C2, C6);
            float2 E0 = cadd(C0, C4), O0 = csub(C0, C4);        // w^0 = 1
            s4[swp(0)]    = make_float4(E0.x, E0.y, O0.x, O0.y);
            float2 w = g_tw[4096]; w.y = -w.y;                  // e^{+i*pi/2}
            float2 E2 = cadd(C2, C6), O2 = cmul(w, csub(C2, C6));
            s4[swp(2048)] = make_float4(E2.x, E2.y, O2.x, O2.y);
        } else {
            const int k2 = 4096 - k;
            float2 Zk  = cadd(A[i][0], A[i][1]);    // Z[k]
            float2 Zk4 = csub(A[i][0], A[i][1]);    // Z[4096+k]
            float2 Zk2 = cadd(A[i][2], A[i][3]);    // Z[4096-k]
            float2 Zm  = csub(A[i][2], A[i][3]);    // Z[8192-k]
            float2 Wk = g_tw[k], Wk2 = g_tw[k2];
            float2 Xk, Xm, Xk2, Xk4;
            herm_unpack(Zk,  Zm,  Wk,  Xk,  Xm);    // bins k, 8192-k
            herm_unpack(Zk2, Zk4, Wk2, Xk2, Xk4);   // bins 4096-k, 4096+k
            float2 Gk  = __ldg(&Hf[k]);        Gk.x  += bs;
            float2 Gm  = __ldg(&Hf[8192 - k]); Gm.x  += bs;
            float2 Gk2 = __ldg(&Hf[k2]);       Gk2.x += bs;
            float2 Gk4 = __ldg(&Hf[4096 + k]); Gk4.x += bs;
            float2 Ck, Cm, Ck2, Ck4;
            herm_repack(cmul(Xk,  Gk),  cmul(Xm,  Gm),  Wk,  Ck,  Cm);
            herm_repack(cmul(Xk2, Gk2), cmul(Xk4, Gk4), Wk2, Ck2, Ck4);
            // inverse radix-2 fold (s=1): p=k -> complex {2k,2k+1} = pair k
            float2 wA = g_tw[2 * k];  wA.y = -wA.y;       // e^{+2*pi*i*k/8192}
            float2 Ea = cadd(Ck, Ck4), Oa = cmul(wA, csub(Ck, Ck4));
            s4[swp(k)]  = make_float4(Ea.x, Ea.y, Oa.x, Oa.y);
            float2 wB = g_tw[2 * k2]; wB.y = -wB.y;
            float2 Eb = cadd(Ck2, Cm), Ob = cmul(wB, csub(Ck2, Cm));
            s4[swp(k2)] = make_float4(Eb.x, Eb.y, Ob.x, Ob.y);
        }
    }
    __syncthreads();

    // inverse: 3 in-place passes + final pass fused with gmem store (r<4 only)
    pass_ip2<+1, 1>(s4);
    pass_ip2<+1, 4>(s4);
    pass_ip2<+1, 7>(s4);
    float4* out4 = reinterpret_cast<float4*>(g_kvt + (size_t)c * L_);
    pass_last_g512(s4, out4);
}

// -------- gate + transpose back: out(b,l,d) = x1(b,l,d) * y_t(b,d,l) -------
__global__ void gate_transpose(const float* __restrict__ x1,
                               float* __restrict__ out){
    __shared__ float tile[64][65];               // [l-local][d-local]
    const int b  = blockIdx.z;
    const int l0 = blockIdx.x * 64;
    const int d0 = blockIdx.y * 64;
    const int tx = threadIdx.x;                  // 0..15
    const int ty = threadIdx.y;                  // 0..15
    #pragma unroll
    for (int i = 0; i < 4; i++){
        int dr = ty + 16 * i;
        float4 ya = *reinterpret_cast<const float4*>(
            g_kvt + ((size_t)b * D_ + d0 + dr) * L_ + l0 + 4 * tx);
        tile[4*tx + 0][dr] = ya.x;
        tile[4*tx + 1][dr] = ya.y;
        tile[4*tx + 2][dr] = ya.z;
        tile[4*tx + 3][dr] = ya.w;
    }
    __syncthreads();
    #pragma unroll
    for (int i = 0; i < 4; i++){
        int lr = ty + 16 * i;
        size_t idx = ((size_t)b * L_ + (l0 + lr)) * D_ + d0 + 4 * tx;
        float4 xa = *reinterpret_cast<const float4*>(x1 + idx);
        float4 o;
        o.x = xa.x * tile[lr][4*tx + 0];
        o.y = xa.y * tile[lr][4*tx + 1];
        o.z = xa.z * tile[lr][4*tx + 2];
        o.w = xa.w * tile[lr][4*tx + 3];
        *reinterpret_cast<float4*>(out + idx) = o;
    }
}

// ---------------------------------------------------------------------------
extern "C" void kernel_launch(void* const* d_in, const int* in_sizes, int n_in,
                              void* d_out, int out_size){
    const float* x1   = (const float*)d_in[0];
    const float* x2   = (const float*)d_in[1];
    const float* v    = (const float*)d_in[2];
    const float* h    = (const float*)d_in[3];
    const float* bias = (const float*)d_in[4];
    float* out = (float*)d_out;

    const int SMEM = M_ * (int)sizeof(float2);   // 65536 B (single buffer)
    cudaFuncSetAttribute(hf_kernel,   cudaFuncAttributeMaxDynamicSharedMemorySize, SMEM);
    cudaFuncSetAttribute(conv_kernel, cudaFuncAttributeMaxDynamicSharedMemorySize, SMEM);

    tw_kernel<<<(M_ + 255) / 256, 256>>>();
    hf_kernel<<<G_, 512, SMEM>>>(h);

    dim3 tgrid(L_ / 64, D_ / 64, B_);
    dim3 tblk(16, 16);
    pregate_transpose<<<tgrid, tblk>>>(x2, v);

    conv_kernel<<<B_ * D_, 512, SMEM>>>(bias);

    gate_transpose<<<tgrid, tblk>>>(x1, out);
}